// round 15
// baseline (speedup 1.0000x reference)
#include <cuda_runtime.h>
#include <cuda_bf16.h>
#include <cuda_fp16.h>
#include <math.h>
#include <cstdint>

#define BATCH 48
#define TLEN  32
#define NCELL 528           // T*(T+1)/2
#define HSZ   512
#define NPROJ 1536          // [A | C | Sh]

#define WT_ELEMS (NPROJ * HSZ)              // 786432
#define X_ELEMS  (BATCH * TLEN * 1024)      // 1572864
#define WL_ELEMS (HSZ * 1024)               // 524288

// ---------------------------------------------------------------------------
// Static scratch (no allocation allowed).
// ---------------------------------------------------------------------------
__device__ __align__(16) float g_AC[(size_t)BATCH * NCELL * 1024];      // A|C fp32
__device__ __align__(16) __half g_Sh[(size_t)BATCH * NCELL * HSZ];      // Sh fp16
__device__ float g_sch[BATCH * NCELL];                                   // chart_s
__device__ __align__(16) float g_ltmp[BATCH * TLEN * HSZ];               // leaf pre-norm
__device__ __align__(16) __nv_bfloat16 g_WT_hi[(size_t)NPROJ * HSZ];     // WcatT hi
__device__ __align__(16) __nv_bfloat16 g_WT_lo[(size_t)NPROJ * HSZ];     // WcatT lo
__device__ __align__(16) __nv_bfloat16 g_chh[(size_t)BATCH * NCELL * HSZ]; // chart hi
__device__ __align__(16) __nv_bfloat16 g_chl[(size_t)BATCH * NCELL * HSZ]; // chart lo
__device__ __align__(16) __nv_bfloat16 g_Xh[(size_t)X_ELEMS];              // x hi
__device__ __align__(16) __nv_bfloat16 g_Xl[(size_t)X_ELEMS];              // x lo
__device__ __align__(16) __nv_bfloat16 g_WLh[(size_t)WL_ELEMS];            // w_leafT hi
__device__ __align__(16) __nv_bfloat16 g_WLl[(size_t)WL_ELEMS];            // w_leafT lo

__host__ __device__ __forceinline__ int offs(int k) {
    return k * TLEN - (k * (k - 1)) / 2;
}

__device__ __forceinline__ uint32_t smem_to_u32(const void* p) {
    uint32_t a;
    asm("{ .reg .u64 t; cvta.to.shared.u64 t, %1; cvt.u32.u64 %0, t; }"
        : "=r"(a) : "l"(p));
    return a;
}
template <int N> __device__ __forceinline__ void cp_wait() {
    asm volatile("cp.async.wait_group %0;" :: "n"(N) : "memory");
}
__device__ __forceinline__ void cp_commit() {
    asm volatile("cp.async.commit_group;" ::: "memory");
}
__device__ __forceinline__ void cp16(uint32_t dst, const void* src, uint32_t srcsz) {
    asm volatile("cp.async.cg.shared.global [%0], [%1], 16, %2;"
                 :: "r"(dst), "l"(src), "r"(srcsz) : "memory");
}
__device__ __forceinline__ void ldm4(uint32_t* r, uint32_t addr) {
    asm volatile("ldmatrix.sync.aligned.m8n8.x4.shared.b16 {%0,%1,%2,%3}, [%4];"
                 : "=r"(r[0]), "=r"(r[1]), "=r"(r[2]), "=r"(r[3]) : "r"(addr));
}
__device__ __forceinline__ void mma16816(float* c, const uint32_t* a,
                                         uint32_t b0, uint32_t b1) {
    asm volatile(
        "mma.sync.aligned.m16n8k16.row.col.f32.bf16.bf16.f32 "
        "{%0,%1,%2,%3}, {%4,%5,%6,%7}, {%8,%9}, {%0,%1,%2,%3};"
        : "+f"(c[0]), "+f"(c[1]), "+f"(c[2]), "+f"(c[3])
        : "r"(a[0]), "r"(a[1]), "r"(a[2]), "r"(a[3]), "r"(b0), "r"(b1));
}

// ---------------------------------------------------------------------------
// Merged pack kernel: fp32 -> bf16 hi/lo for Wcat^T, x, w_leaf^T.
// ---------------------------------------------------------------------------
__global__ void pack_all(const float* __restrict__ w_comp,
                         const float* __restrict__ s_bil,
                         const float* __restrict__ x,
                         const float* __restrict__ w_leaf) {
    int idx = blockIdx.x * 256 + threadIdx.x;
    if (idx < WT_ELEMS) {
        int j = idx >> 9;
        int k = idx & 511;
        float v;
        if (j < HSZ)            v = w_comp[k * HSZ + j];
        else if (j < 2 * HSZ)   v = w_comp[(HSZ + k) * HSZ + (j - HSZ)];
        else                    v = s_bil[k * HSZ + (j - 2 * HSZ)];
        __nv_bfloat16 hi = __float2bfloat16(v);
        g_WT_hi[idx] = hi;
        g_WT_lo[idx] = __float2bfloat16(v - __bfloat162float(hi));
    } else if (idx < WT_ELEMS + X_ELEMS) {
        int i = idx - WT_ELEMS;
        float v = x[i];
        __nv_bfloat16 hi = __float2bfloat16(v);
        g_Xh[i] = hi;
        g_Xl[i] = __float2bfloat16(v - __bfloat162float(hi));
    } else {
        int i = idx - WT_ELEMS - X_ELEMS;
        int n = i >> 10;
        int k = i & 1023;
        float v = w_leaf[k * HSZ + n];
        __nv_bfloat16 hi = __float2bfloat16(v);
        g_WLh[i] = hi;
        g_WLl[i] = __float2bfloat16(v - __bfloat162float(hi));
    }
}

// ---------------------------------------------------------------------------
// GEMM tiling (R12-proven): CTA 64x64, 128 thr (2x2 warps, warp 32x32), BK=32,
// 3-stage cp.async, one sync/iter. A: 80B padded rows. B: 64B rows + XOR
// chunk swizzle (phys_chunk = c ^ ((row>>1)&3)). 54KB smem -> 4 CTAs/SM.
// ---------------------------------------------------------------------------
#define PROWB   80
#define BROWB   64
#define POFF_AH 0
#define POFF_AL 5120
#define POFF_BH 10240
#define POFF_BL 14336
#define PSTAGE  18432
#define NSTAGE  3
#define DSMEM   (NSTAGE * PSTAGE)        // 55296

__device__ __forceinline__ uint32_t bswz(int row, int c) {
    return (uint32_t)(row * BROWB) + ((uint32_t)(c ^ ((row >> 1) & 3)) << 4);
}

// Full-precision chunk: 3x bf16 split (hi*hi + hi*lo + lo*hi).
__device__ __forceinline__ void gemm_chunk(uint32_t stage, uint32_t aRowOff,
                                           int bRow0, int cSel,
                                           float acc[2][4][4]) {
#pragma unroll
    for (int kh = 0; kh < 2; kh++) {
        uint32_t kb = kh * 32;
        int c = kh * 2 + cSel;
        uint32_t ahi[2][4], alo[2][4], bhi[2][4], blo[2][4];
#pragma unroll
        for (int mi = 0; mi < 2; mi++) {
            uint32_t ao = mi * 16 * PROWB + kb;
            ldm4(ahi[mi], stage + POFF_AH + aRowOff + ao);
            ldm4(alo[mi], stage + POFF_AL + aRowOff + ao);
        }
#pragma unroll
        for (int nj = 0; nj < 2; nj++) {
            uint32_t bo = bswz(bRow0 + nj * 16, c);
            ldm4(bhi[nj], stage + POFF_BH + bo);
            ldm4(blo[nj], stage + POFF_BL + bo);
        }
#pragma unroll
        for (int mi = 0; mi < 2; mi++) {
#pragma unroll
            for (int ni = 0; ni < 4; ni++) {
                int nj = ni >> 1, sel = ni & 1;
                uint32_t bh0 = bhi[nj][sel], bh1 = bhi[nj][sel + 2];
                uint32_t bl0 = blo[nj][sel], bl1 = blo[nj][sel + 2];
                mma16816(acc[mi][ni], ahi[mi], bh0, bh1);
                mma16816(acc[mi][ni], ahi[mi], bl0, bl1);
                mma16816(acc[mi][ni], alo[mi], bh0, bh1);
            }
        }
    }
}

// Score-precision chunk: hi*hi only (Sh tiles; feeds fp16 scores).
__device__ __forceinline__ void gemm_chunk_sh(uint32_t stage, uint32_t aRowOff,
                                              int bRow0, int cSel,
                                              float acc[2][4][4]) {
#pragma unroll
    for (int kh = 0; kh < 2; kh++) {
        uint32_t kb = kh * 32;
        int c = kh * 2 + cSel;
        uint32_t ahi[2][4], bhi[2][4];
#pragma unroll
        for (int mi = 0; mi < 2; mi++)
            ldm4(ahi[mi], stage + POFF_AH + aRowOff + mi * 16 * PROWB + kb);
#pragma unroll
        for (int nj = 0; nj < 2; nj++)
            ldm4(bhi[nj], stage + POFF_BH + bswz(bRow0 + nj * 16, c));
#pragma unroll
        for (int mi = 0; mi < 2; mi++) {
#pragma unroll
            for (int ni = 0; ni < 4; ni++) {
                int nj = ni >> 1, sel = ni & 1;
                mma16816(acc[mi][ni], ahi[mi], bhi[nj][sel], bhi[nj][sel + 2]);
            }
        }
    }
}

// ---------------------------------------------------------------------------
// Projection: out[cell] = h[cell] @ Wcat (512 -> 1536), gathered rows.
// N-tiles 0..15 -> g_AC (fp32, 3-term). N-tiles 16..23 -> g_Sh (fp16, 1-term).
// ---------------------------------------------------------------------------
__global__ __launch_bounds__(128, 4)
void proj_mma(int off, int L, int M) {
    extern __shared__ __align__(16) char dsm[];
    uint32_t sbase = smem_to_u32(dsm);
    __shared__ int rowCell[64];

    int tid = threadIdx.x, wid = tid >> 5, lane = tid & 31;
    int n0 = blockIdx.x * 64;
    int m0 = blockIdx.y * 64;
    bool isSh = (n0 >= 2 * HSZ);
    if (tid < 64) {
        int r = m0 + tid;
        rowCell[tid] = (r < M) ? ((r / L) * NCELL + off + (r % L)) : -1;
    }
    __syncthreads();

    auto issue = [&](int s) {
        uint32_t stage = sbase + (s % NSTAGE) * PSTAGE;
        int kc = s * 32;
        int nA = isSh ? 2 : 4;    // hi only for Sh tiles
#pragma unroll 4
        for (int i = 0; i < nA; i++) {                    // A hi(/lo)
            int c = tid + i * 128;
            int half = c >> 8;
            int rr = c & 255;
            int row = rr >> 2, q = rr & 3;
            uint32_t dst = stage + (half ? POFF_AL : POFF_AH) + row * PROWB + q * 16;
            int cell = rowCell[row];
            const __nv_bfloat16* sp = (half ? g_chl : g_chh);
            const void* src = sp + ((size_t)(cell < 0 ? 0 : cell) * HSZ + kc + q * 8);
            cp16(dst, src, cell < 0 ? 0u : 16u);
        }
#pragma unroll 4
        for (int i = 0; i < nA; i++) {                    // B hi(/lo)
            int c = tid + i * 128;
            int half = c >> 8;
            int rr = c & 255;
            int row = rr >> 2, q = rr & 3;
            uint32_t dst = stage + (half ? POFF_BL : POFF_BH) + bswz(row, q);
            const __nv_bfloat16* sp = (half ? g_WT_lo : g_WT_hi);
            cp16(dst, sp + ((size_t)(n0 + row) * HSZ + kc + q * 8), 16u);
        }
        cp_commit();
    };

    float acc[2][4][4];
#pragma unroll
    for (int mi = 0; mi < 2; mi++)
#pragma unroll
        for (int ni = 0; ni < 4; ni++)
#pragma unroll
            for (int q = 0; q < 4; q++) acc[mi][ni][q] = 0.f;

    int wm = wid & 1, wn = wid >> 1;       // 2 x 2 warp grid
    int laneRow = lane & 15;
    int cSel = lane >> 4;
    uint32_t aRowOff = (uint32_t)(wm * 32 + laneRow) * PROWB + (uint32_t)cSel * 16;
    int bRow0 = wn * 32 + laneRow;

    const int KITER = 16;
    issue(0); issue(1);
    for (int kt = 0; kt < KITER; kt++) {
        if (kt + 1 < KITER) cp_wait<1>(); else cp_wait<0>();
        __syncthreads();
        if (kt + 2 < KITER) issue(kt + 2);
        uint32_t stage = sbase + (kt % NSTAGE) * PSTAGE;
        if (isSh) gemm_chunk_sh(stage, aRowOff, bRow0, cSel, acc);
        else      gemm_chunk(stage, aRowOff, bRow0, cSel, acc);
    }

    int qrow = lane >> 2, qcol = (lane & 3) * 2;
#pragma unroll
    for (int mi = 0; mi < 2; mi++) {
        int r0 = wm * 32 + mi * 16 + qrow;
        int c0 = rowCell[r0];
        int c1 = rowCell[r0 + 8];
#pragma unroll
        for (int ni = 0; ni < 4; ni++) {
            int colIn = wn * 32 + ni * 8 + qcol;
            if (!isSh) {
                int col = n0 + colIn;
                if (c0 >= 0)
                    *(float2*)(g_AC + (size_t)c0 * 1024 + col) =
                        make_float2(acc[mi][ni][0], acc[mi][ni][1]);
                if (c1 >= 0)
                    *(float2*)(g_AC + (size_t)c1 * 1024 + col) =
                        make_float2(acc[mi][ni][2], acc[mi][ni][3]);
            } else {
                int col = (n0 - 2 * HSZ) + colIn;
                if (c0 >= 0)
                    *(__half2*)(g_Sh + (size_t)c0 * HSZ + col) =
                        __floats2half2_rn(acc[mi][ni][0], acc[mi][ni][1]);
                if (c1 >= 0)
                    *(__half2*)(g_Sh + (size_t)c1 * HSZ + col) =
                        __floats2half2_rn(acc[mi][ni][2], acc[mi][ni][3]);
            }
        }
    }
}

// ---------------------------------------------------------------------------
// Leaf GEMM via mma: g_ltmp = relu(x @ w_leaf + b). M=1536, N=512, K=1024.
// ---------------------------------------------------------------------------
__global__ __launch_bounds__(128, 4)
void leaf_mma(const float* __restrict__ bias) {
    extern __shared__ __align__(16) char dsm[];
    uint32_t sbase = smem_to_u32(dsm);
    int tid = threadIdx.x, wid = tid >> 5, lane = tid & 31;
    int n0 = blockIdx.x * 64;     // 8
    int m0 = blockIdx.y * 64;     // 24

    auto issue = [&](int s) {
        uint32_t stage = sbase + (s % NSTAGE) * PSTAGE;
        int kc = s * 32;
#pragma unroll
        for (int i = 0; i < 4; i++) {
            int c = tid + i * 128;
            int half = c >> 8;
            int rr = c & 255;
            int row = rr >> 2, q = rr & 3;
            uint32_t dst = stage + (half ? POFF_AL : POFF_AH) + row * PROWB + q * 16;
            const __nv_bfloat16* sp = (half ? g_Xl : g_Xh);
            cp16(dst, sp + ((size_t)(m0 + row) * 1024 + kc + q * 8), 16u);
        }
#pragma unroll
        for (int i = 0; i < 4; i++) {
            int c = tid + i * 128;
            int half = c >> 8;
            int rr = c & 255;
            int row = rr >> 2, q = rr & 3;
            uint32_t dst = stage + (half ? POFF_BL : POFF_BH) + bswz(row, q);
            const __nv_bfloat16* sp = (half ? g_WLl : g_WLh);
            cp16(dst, sp + ((size_t)(n0 + row) * 1024 + kc + q * 8), 16u);
        }
        cp_commit();
    };

    float acc[2][4][4];
#pragma unroll
    for (int mi = 0; mi < 2; mi++)
#pragma unroll
        for (int ni = 0; ni < 4; ni++)
#pragma unroll
            for (int q = 0; q < 4; q++) acc[mi][ni][q] = 0.f;

    int wm = wid & 1, wn = wid >> 1;
    int laneRow = lane & 15;
    int cSel = lane >> 4;
    uint32_t aRowOff = (uint32_t)(wm * 32 + laneRow) * PROWB + (uint32_t)cSel * 16;
    int bRow0 = wn * 32 + laneRow;

    const int KITER = 32;
    issue(0); issue(1);
    for (int kt = 0; kt < KITER; kt++) {
        if (kt + 1 < KITER) cp_wait<1>(); else cp_wait<0>();
        __syncthreads();
        if (kt + 2 < KITER) issue(kt + 2);
        gemm_chunk(sbase + (kt % NSTAGE) * PSTAGE, aRowOff, bRow0, cSel, acc);
    }

    int qrow = lane >> 2, qcol = (lane & 3) * 2;
#pragma unroll
    for (int mi = 0; mi < 2; mi++) {
        int r0 = m0 + wm * 32 + mi * 16 + qrow;
#pragma unroll
        for (int ni = 0; ni < 4; ni++) {
            int col = n0 + wn * 32 + ni * 8 + qcol;
            float2 bc = *(const float2*)&bias[col];
            *(float2*)(g_ltmp + (size_t)r0 * HSZ + col) =
                make_float2(fmaxf(acc[mi][ni][0] + bc.x, 0.f),
                            fmaxf(acc[mi][ni][1] + bc.y, 0.f));
            *(float2*)(g_ltmp + (size_t)(r0 + 8) * HSZ + col) =
                make_float2(fmaxf(acc[mi][ni][2] + bc.x, 0.f),
                            fmaxf(acc[mi][ni][3] + bc.y, 0.f));
        }
    }
}

// ---------------------------------------------------------------------------
// Normalize leaf rows -> chart cells (b, t) fp32 + bf16 hi/lo; zero leaf scores.
// ---------------------------------------------------------------------------
__global__ void leaf_norm(float* __restrict__ chart) {
    int r = blockIdx.x;
    int b = r >> 5, t = r & 31;
    int tid = threadIdx.x;            // 128
    const float4* src = (const float4*)(g_ltmp + (size_t)r * HSZ);
    float4 v = src[tid];
    float ss = v.x * v.x + v.y * v.y + v.z * v.z + v.w * v.w;
    __shared__ float red[4];
    __shared__ float s_inv;
    int w = tid >> 5, lane = tid & 31;
#pragma unroll
    for (int o = 16; o > 0; o >>= 1) ss += __shfl_xor_sync(0xffffffffu, ss, o);
    if (lane == 0) red[w] = ss;
    __syncthreads();
    if (tid == 0) {
        float tt = red[0] + red[1] + red[2] + red[3];
        s_inv = 1.f / fmaxf(sqrtf(tt), 1e-12f);
        g_sch[b * NCELL + t] = 0.f;
    }
    __syncthreads();
    float inv = s_inv;
    v.x *= inv; v.y *= inv; v.z *= inv; v.w *= inv;
    size_t base = ((size_t)b * NCELL + t) * HSZ;
    *(float4*)(chart + base + tid * 4) = v;
    float f[4] = {v.x, v.y, v.z, v.w};
    __align__(8) __nv_bfloat16 hi[4], lo[4];
#pragma unroll
    for (int i = 0; i < 4; i++) {
        hi[i] = __float2bfloat16(f[i]);
        lo[i] = __float2bfloat16(f[i] - __bfloat162float(hi[i]));
    }
    *(uint2*)(g_chh + base + tid * 4) = *(const uint2*)hi;
    *(uint2*)(g_chl + base + tid * 4) = *(const uint2*)lo;
}

// ---------------------------------------------------------------------------
// Combine: one block (256 threads) per output cell (b, pos) at `level`.
// Pass 1: fp16 Sh x bf16 h. Pass 2: float4 per thread (128 active lanes).
// ---------------------------------------------------------------------------
__global__ __launch_bounds__(256)
void combine_kernel2(float* __restrict__ chart,
                     const float* __restrict__ b_comp,
                     int level) {
    int L = TLEN - level;
    int cidx = blockIdx.x;
    int b = cidx / L, pos = cidx - b * L;
    int cell = b * NCELL + offs(level) + pos;

    __shared__ float sv[32];
    __shared__ float pv[32];
    __shared__ float red[4];
    __shared__ float s_inv;

    int tid = threadIdx.x, w = tid >> 5, lane = tid & 31;

    for (int n = w; n < level; n += 8) {
        int lcell = b * NCELL + offs(n) + pos;
        int rcell = b * NCELL + offs(level - 1 - n) + pos + n + 1;
        const uint2* Sp = (const uint2*)(g_Sh + (size_t)lcell * HSZ);
        const uint2* Hp = (const uint2*)(g_chh + (size_t)rcell * HSZ);
        float d = 0.f;
#pragma unroll
        for (int i = lane; i < 128; i += 32) {
            uint2 sraw = __ldg(Sp + i);
            uint2 hraw = __ldg(Hp + i);
            float2 s0 = __half22float2(*(__half2*)&sraw.x);
            float2 s1 = __half22float2(*(__half2*)&sraw.y);
            float2 h0 = __bfloat1622float2(*(__nv_bfloat162*)&hraw.x);
            float2 h1 = __bfloat1622float2(*(__nv_bfloat162*)&hraw.y);
            d += s0.x * h0.x + s0.y * h0.y + s1.x * h1.x + s1.y * h1.y;
        }
#pragma unroll
        for (int o = 16; o > 0; o >>= 1) d += __shfl_xor_sync(0xffffffffu, d, o);
        if (lane == 0) sv[n] = d + g_sch[lcell] + g_sch[rcell];
    }
    __syncthreads();

    if (w == 0) {
        float s = (lane < level) ? sv[lane] : -1e30f;
        float m = s;
#pragma unroll
        for (int o = 16; o > 0; o >>= 1) m = fmaxf(m, __shfl_xor_sync(0xffffffffu, m, o));
        float e = (lane < level) ? expf(s - m) : 0.f;
        float se = e;
#pragma unroll
        for (int o = 16; o > 0; o >>= 1) se += __shfl_xor_sync(0xffffffffu, se, o);
        float p = e / se;
        pv[lane] = p;
        float sp = (lane < level) ? s * p : 0.f;
#pragma unroll
        for (int o = 16; o > 0; o >>= 1) sp += __shfl_xor_sync(0xffffffffu, sp, o);
        if (lane == 0 && level < TLEN - 1) g_sch[cell] = sp;
    }
    __syncthreads();

    float4 acc = make_float4(0.f, 0.f, 0.f, 0.f);
    int j = (tid & 127) * 4;
    if (tid < 128) {
        const float4 bc = *(const float4*)&b_comp[j];
        int base0 = b * NCELL + pos;
#pragma unroll 4
        for (int n = 0; n < level; n++) {
            int lcell = base0 + offs(n);
            int rcell = base0 + offs(level - 1 - n) + n + 1;
            float4 A = __ldg((const float4*)(g_AC + (size_t)lcell * 1024 + j));
            float4 C = __ldg((const float4*)(g_AC + (size_t)rcell * 1024 + HSZ + j));
            float p = pv[n];
            acc.x += p * fmaxf(A.x + C.x + bc.x, 0.f);
            acc.y += p * fmaxf(A.y + C.y + bc.y, 0.f);
            acc.z += p * fmaxf(A.z + C.z + bc.z, 0.f);
            acc.w += p * fmaxf(A.w + C.w + bc.w, 0.f);
        }
        float ss = acc.x * acc.x + acc.y * acc.y + acc.z * acc.z + acc.w * acc.w;
#pragma unroll
        for (int o = 16; o > 0; o >>= 1) ss += __shfl_xor_sync(0xffffffffu, ss, o);
        if (lane == 0) red[w] = ss;
    }
    __syncthreads();
    if (tid == 0) {
        float t = red[0] + red[1] + red[2] + red[3];
        s_inv = 1.f / fmaxf(sqrtf(t), 1e-12f);
    }
    __syncthreads();
    if (tid < 128) {
        float inv = s_inv;
        float4 v = make_float4(acc.x * inv, acc.y * inv, acc.z * inv, acc.w * inv);
        size_t base = (size_t)cell * HSZ;
        *(float4*)(chart + base + j) = v;
        if (level < TLEN - 1) {
            float f[4] = {v.x, v.y, v.z, v.w};
            __align__(8) __nv_bfloat16 hi[4], lo[4];
#pragma unroll
            for (int i = 0; i < 4; i++) {
                hi[i] = __float2bfloat16(f[i]);
                lo[i] = __float2bfloat16(f[i] - __bfloat162float(hi[i]));
            }
            *(uint2*)(g_chh + base + j) = *(const uint2*)hi;
            *(uint2*)(g_chl + base + j) = *(const uint2*)lo;
        }
    }
}

// ---------------------------------------------------------------------------
extern "C" void kernel_launch(void* const* d_in, const int* in_sizes, int n_in,
                              void* d_out, int out_size) {
    const float* x      = (const float*)d_in[0];
    const float* w_leaf = (const float*)d_in[1];
    const float* b_leaf = (const float*)d_in[2];
    const float* w_comp = (const float*)d_in[3];
    const float* b_comp = (const float*)d_in[4];
    const float* s_bil  = (const float*)d_in[5];
    float* chart = (float*)d_out;

    (void)in_sizes; (void)n_in; (void)out_size;

    cudaFuncSetAttribute(proj_mma, cudaFuncAttributeMaxDynamicSharedMemorySize, DSMEM);
    cudaFuncSetAttribute(leaf_mma, cudaFuncAttributeMaxDynamicSharedMemorySize, DSMEM);

    pack_all<<<(WT_ELEMS + X_ELEMS + WL_ELEMS) / 256, 256>>>(
        w_comp, s_bil, x, w_leaf);

    leaf_mma<<<dim3(HSZ / 64, (BATCH * TLEN) / 64), 128, DSMEM>>>(b_leaf);
    leaf_norm<<<BATCH * TLEN, 128>>>(chart);
    proj_mma<<<dim3(NPROJ / 64, (BATCH * TLEN + 63) / 64), 128, DSMEM>>>(
        0, TLEN, BATCH * TLEN);

    for (int level = 1; level < TLEN; level++) {
        int L = TLEN - level;
        combine_kernel2<<<BATCH * L, 256>>>(chart, b_comp, level);
        if (level < TLEN - 1) {
            int M = BATCH * L;
            proj_mma<<<dim3(NPROJ / 64, (M + 63) / 64), 128, DSMEM>>>(
                offs(level), L, M);
        }
    }
}

// round 16
// speedup vs baseline: 1.0719x; 1.0719x over previous
#include <cuda_runtime.h>
#include <cuda_bf16.h>
#include <cuda_fp16.h>
#include <math.h>
#include <cstdint>

#define BATCH 48
#define TLEN  32
#define NCELL 528           // T*(T+1)/2
#define HSZ   512
#define NPROJ 1536          // [A | C | Sh]

#define WT_ELEMS (NPROJ * HSZ)              // 786432
#define X_ELEMS  (BATCH * TLEN * 1024)      // 1572864
#define WL_ELEMS (HSZ * 1024)               // 524288

// ---------------------------------------------------------------------------
// Static scratch (no allocation allowed).
// ---------------------------------------------------------------------------
__device__ __align__(16) __half g_ACh[(size_t)BATCH * NCELL * 1024];    // A|C fp16
__device__ __align__(16) __half g_Sh[(size_t)BATCH * NCELL * HSZ];      // Sh fp16
__device__ float g_sch[BATCH * NCELL];                                   // chart_s
__device__ __align__(16) float g_ltmp[BATCH * TLEN * HSZ];               // leaf pre-norm
__device__ __align__(16) __nv_bfloat16 g_WT_hi[(size_t)NPROJ * HSZ];     // WcatT hi
__device__ __align__(16) __nv_bfloat16 g_WT_lo[(size_t)NPROJ * HSZ];     // WcatT lo
__device__ __align__(16) __nv_bfloat16 g_chh[(size_t)BATCH * NCELL * HSZ]; // chart hi
__device__ __align__(16) __nv_bfloat16 g_chl[(size_t)BATCH * NCELL * HSZ]; // chart lo
__device__ __align__(16) __nv_bfloat16 g_Xh[(size_t)X_ELEMS];              // x hi
__device__ __align__(16) __nv_bfloat16 g_Xl[(size_t)X_ELEMS];              // x lo
__device__ __align__(16) __nv_bfloat16 g_WLh[(size_t)WL_ELEMS];            // w_leafT hi
__device__ __align__(16) __nv_bfloat16 g_WLl[(size_t)WL_ELEMS];            // w_leafT lo

__host__ __device__ __forceinline__ int offs(int k) {
    return k * TLEN - (k * (k - 1)) / 2;
}

__device__ __forceinline__ uint32_t smem_to_u32(const void* p) {
    uint32_t a;
    asm("{ .reg .u64 t; cvta.to.shared.u64 t, %1; cvt.u32.u64 %0, t; }"
        : "=r"(a) : "l"(p));
    return a;
}
template <int N> __device__ __forceinline__ void cp_wait() {
    asm volatile("cp.async.wait_group %0;" :: "n"(N) : "memory");
}
__device__ __forceinline__ void cp_commit() {
    asm volatile("cp.async.commit_group;" ::: "memory");
}
__device__ __forceinline__ void cp16(uint32_t dst, const void* src, uint32_t srcsz) {
    asm volatile("cp.async.cg.shared.global [%0], [%1], 16, %2;"
                 :: "r"(dst), "l"(src), "r"(srcsz) : "memory");
}
__device__ __forceinline__ void ldm4(uint32_t* r, uint32_t addr) {
    asm volatile("ldmatrix.sync.aligned.m8n8.x4.shared.b16 {%0,%1,%2,%3}, [%4];"
                 : "=r"(r[0]), "=r"(r[1]), "=r"(r[2]), "=r"(r[3]) : "r"(addr));
}
__device__ __forceinline__ void mma16816(float* c, const uint32_t* a,
                                         uint32_t b0, uint32_t b1) {
    asm volatile(
        "mma.sync.aligned.m16n8k16.row.col.f32.bf16.bf16.f32 "
        "{%0,%1,%2,%3}, {%4,%5,%6,%7}, {%8,%9}, {%0,%1,%2,%3};"
        : "+f"(c[0]), "+f"(c[1]), "+f"(c[2]), "+f"(c[3])
        : "r"(a[0]), "r"(a[1]), "r"(a[2]), "r"(a[3]), "r"(b0), "r"(b1));
}

// ---------------------------------------------------------------------------
// Merged pack kernel: fp32 -> bf16 hi/lo for Wcat^T, x, w_leaf^T.
// ---------------------------------------------------------------------------
__global__ void pack_all(const float* __restrict__ w_comp,
                         const float* __restrict__ s_bil,
                         const float* __restrict__ x,
                         const float* __restrict__ w_leaf) {
    int idx = blockIdx.x * 256 + threadIdx.x;
    if (idx < WT_ELEMS) {
        int j = idx >> 9;
        int k = idx & 511;
        float v;
        if (j < HSZ)            v = w_comp[k * HSZ + j];
        else if (j < 2 * HSZ)   v = w_comp[(HSZ + k) * HSZ + (j - HSZ)];
        else                    v = s_bil[k * HSZ + (j - 2 * HSZ)];
        __nv_bfloat16 hi = __float2bfloat16(v);
        g_WT_hi[idx] = hi;
        g_WT_lo[idx] = __float2bfloat16(v - __bfloat162float(hi));
    } else if (idx < WT_ELEMS + X_ELEMS) {
        int i = idx - WT_ELEMS;
        float v = x[i];
        __nv_bfloat16 hi = __float2bfloat16(v);
        g_Xh[i] = hi;
        g_Xl[i] = __float2bfloat16(v - __bfloat162float(hi));
    } else {
        int i = idx - WT_ELEMS - X_ELEMS;
        int n = i >> 10;
        int k = i & 1023;
        float v = w_leaf[k * HSZ + n];
        __nv_bfloat16 hi = __float2bfloat16(v);
        g_WLh[i] = hi;
        g_WLl[i] = __float2bfloat16(v - __bfloat162float(hi));
    }
}

// ---------------------------------------------------------------------------
// GEMM tiling (R12-proven): CTA 64x64, 128 thr (2x2 warps, warp 32x32), BK=32,
// 3-stage cp.async, one sync/iter. A: 80B padded rows. B: 64B rows + XOR
// chunk swizzle (phys_chunk = c ^ ((row>>1)&3)). 54KB smem -> 4 CTAs/SM.
// ---------------------------------------------------------------------------
#define PROWB   80
#define BROWB   64
#define POFF_AH 0
#define POFF_AL 5120
#define POFF_BH 10240
#define POFF_BL 14336
#define PSTAGE  18432
#define NSTAGE  3
#define DSMEM   (NSTAGE * PSTAGE)        // 55296

__device__ __forceinline__ uint32_t bswz(int row, int c) {
    return (uint32_t)(row * BROWB) + ((uint32_t)(c ^ ((row >> 1) & 3)) << 4);
}

// 3x bf16 split chunk (hi*hi + hi*lo + lo*hi).
__device__ __forceinline__ void gemm_chunk(uint32_t stage, uint32_t aRowOff,
                                           int bRow0, int cSel,
                                           float acc[2][4][4]) {
#pragma unroll
    for (int kh = 0; kh < 2; kh++) {
        uint32_t kb = kh * 32;
        int c = kh * 2 + cSel;
        uint32_t ahi[2][4], alo[2][4], bhi[2][4], blo[2][4];
#pragma unroll
        for (int mi = 0; mi < 2; mi++) {
            uint32_t ao = mi * 16 * PROWB + kb;
            ldm4(ahi[mi], stage + POFF_AH + aRowOff + ao);
            ldm4(alo[mi], stage + POFF_AL + aRowOff + ao);
        }
#pragma unroll
        for (int nj = 0; nj < 2; nj++) {
            uint32_t bo = bswz(bRow0 + nj * 16, c);
            ldm4(bhi[nj], stage + POFF_BH + bo);
            ldm4(blo[nj], stage + POFF_BL + bo);
        }
#pragma unroll
        for (int mi = 0; mi < 2; mi++) {
#pragma unroll
            for (int ni = 0; ni < 4; ni++) {
                int nj = ni >> 1, sel = ni & 1;
                uint32_t bh0 = bhi[nj][sel], bh1 = bhi[nj][sel + 2];
                uint32_t bl0 = blo[nj][sel], bl1 = blo[nj][sel + 2];
                mma16816(acc[mi][ni], ahi[mi], bh0, bh1);
                mma16816(acc[mi][ni], ahi[mi], bl0, bl1);
                mma16816(acc[mi][ni], alo[mi], bh0, bh1);
            }
        }
    }
}

// ---------------------------------------------------------------------------
// Projection: out[cell] = h[cell] @ Wcat (512 -> 1536), gathered rows.
// N-tiles 0..15 -> g_ACh (fp16); N-tiles 16..23 -> g_Sh (fp16).
// ---------------------------------------------------------------------------
__global__ __launch_bounds__(128, 4)
void proj_mma(int off, int L, int M) {
    extern __shared__ __align__(16) char dsm[];
    uint32_t sbase = smem_to_u32(dsm);
    __shared__ int rowCell[64];

    int tid = threadIdx.x, wid = tid >> 5, lane = tid & 31;
    int n0 = blockIdx.x * 64;
    int m0 = blockIdx.y * 64;
    if (tid < 64) {
        int r = m0 + tid;
        rowCell[tid] = (r < M) ? ((r / L) * NCELL + off + (r % L)) : -1;
    }
    __syncthreads();

    auto issue = [&](int s) {
        uint32_t stage = sbase + (s % NSTAGE) * PSTAGE;
        int kc = s * 32;
#pragma unroll
        for (int i = 0; i < 4; i++) {                     // A hi/lo: 512 chunks
            int c = tid + i * 128;
            int half = c >> 8;
            int rr = c & 255;
            int row = rr >> 2, q = rr & 3;
            uint32_t dst = stage + (half ? POFF_AL : POFF_AH) + row * PROWB + q * 16;
            int cell = rowCell[row];
            const __nv_bfloat16* sp = (half ? g_chl : g_chh);
            const void* src = sp + ((size_t)(cell < 0 ? 0 : cell) * HSZ + kc + q * 8);
            cp16(dst, src, cell < 0 ? 0u : 16u);
        }
#pragma unroll
        for (int i = 0; i < 4; i++) {                     // B hi/lo: 512 chunks
            int c = tid + i * 128;
            int half = c >> 8;
            int rr = c & 255;
            int row = rr >> 2, q = rr & 3;
            uint32_t dst = stage + (half ? POFF_BL : POFF_BH) + bswz(row, q);
            const __nv_bfloat16* sp = (half ? g_WT_lo : g_WT_hi);
            cp16(dst, sp + ((size_t)(n0 + row) * HSZ + kc + q * 8), 16u);
        }
        cp_commit();
    };

    float acc[2][4][4];
#pragma unroll
    for (int mi = 0; mi < 2; mi++)
#pragma unroll
        for (int ni = 0; ni < 4; ni++)
#pragma unroll
            for (int q = 0; q < 4; q++) acc[mi][ni][q] = 0.f;

    int wm = wid & 1, wn = wid >> 1;       // 2 x 2 warp grid
    int laneRow = lane & 15;
    int cSel = lane >> 4;
    uint32_t aRowOff = (uint32_t)(wm * 32 + laneRow) * PROWB + (uint32_t)cSel * 16;
    int bRow0 = wn * 32 + laneRow;

    const int KITER = 16;
    issue(0); issue(1);
    for (int kt = 0; kt < KITER; kt++) {
        if (kt + 1 < KITER) cp_wait<1>(); else cp_wait<0>();
        __syncthreads();
        if (kt + 2 < KITER) issue(kt + 2);
        gemm_chunk(sbase + (kt % NSTAGE) * PSTAGE, aRowOff, bRow0, cSel, acc);
    }

    int qrow = lane >> 2, qcol = (lane & 3) * 2;
    bool isSh = (n0 >= 2 * HSZ);
#pragma unroll
    for (int mi = 0; mi < 2; mi++) {
        int r0 = wm * 32 + mi * 16 + qrow;
        int c0 = rowCell[r0];
        int c1 = rowCell[r0 + 8];
#pragma unroll
        for (int ni = 0; ni < 4; ni++) {
            int colIn = wn * 32 + ni * 8 + qcol;
            if (!isSh) {
                int col = n0 + colIn;
                if (c0 >= 0)
                    *(__half2*)(g_ACh + (size_t)c0 * 1024 + col) =
                        __floats2half2_rn(acc[mi][ni][0], acc[mi][ni][1]);
                if (c1 >= 0)
                    *(__half2*)(g_ACh + (size_t)c1 * 1024 + col) =
                        __floats2half2_rn(acc[mi][ni][2], acc[mi][ni][3]);
            } else {
                int col = (n0 - 2 * HSZ) + colIn;
                if (c0 >= 0)
                    *(__half2*)(g_Sh + (size_t)c0 * HSZ + col) =
                        __floats2half2_rn(acc[mi][ni][0], acc[mi][ni][1]);
                if (c1 >= 0)
                    *(__half2*)(g_Sh + (size_t)c1 * HSZ + col) =
                        __floats2half2_rn(acc[mi][ni][2], acc[mi][ni][3]);
            }
        }
    }
}

// ---------------------------------------------------------------------------
// Leaf GEMM via mma: g_ltmp = relu(x @ w_leaf + b). M=1536, N=512, K=1024.
// ---------------------------------------------------------------------------
__global__ __launch_bounds__(128, 4)
void leaf_mma(const float* __restrict__ bias) {
    extern __shared__ __align__(16) char dsm[];
    uint32_t sbase = smem_to_u32(dsm);
    int tid = threadIdx.x, wid = tid >> 5, lane = tid & 31;
    int n0 = blockIdx.x * 64;     // 8
    int m0 = blockIdx.y * 64;     // 24

    auto issue = [&](int s) {
        uint32_t stage = sbase + (s % NSTAGE) * PSTAGE;
        int kc = s * 32;
#pragma unroll
        for (int i = 0; i < 4; i++) {
            int c = tid + i * 128;
            int half = c >> 8;
            int rr = c & 255;
            int row = rr >> 2, q = rr & 3;
            uint32_t dst = stage + (half ? POFF_AL : POFF_AH) + row * PROWB + q * 16;
            const __nv_bfloat16* sp = (half ? g_Xl : g_Xh);
            cp16(dst, sp + ((size_t)(m0 + row) * 1024 + kc + q * 8), 16u);
        }
#pragma unroll
        for (int i = 0; i < 4; i++) {
            int c = tid + i * 128;
            int half = c >> 8;
            int rr = c & 255;
            int row = rr >> 2, q = rr & 3;
            uint32_t dst = stage + (half ? POFF_BL : POFF_BH) + bswz(row, q);
            const __nv_bfloat16* sp = (half ? g_WLl : g_WLh);
            cp16(dst, sp + ((size_t)(n0 + row) * 1024 + kc + q * 8), 16u);
        }
        cp_commit();
    };

    float acc[2][4][4];
#pragma unroll
    for (int mi = 0; mi < 2; mi++)
#pragma unroll
        for (int ni = 0; ni < 4; ni++)
#pragma unroll
            for (int q = 0; q < 4; q++) acc[mi][ni][q] = 0.f;

    int wm = wid & 1, wn = wid >> 1;
    int laneRow = lane & 15;
    int cSel = lane >> 4;
    uint32_t aRowOff = (uint32_t)(wm * 32 + laneRow) * PROWB + (uint32_t)cSel * 16;
    int bRow0 = wn * 32 + laneRow;

    const int KITER = 32;
    issue(0); issue(1);
    for (int kt = 0; kt < KITER; kt++) {
        if (kt + 1 < KITER) cp_wait<1>(); else cp_wait<0>();
        __syncthreads();
        if (kt + 2 < KITER) issue(kt + 2);
        gemm_chunk(sbase + (kt % NSTAGE) * PSTAGE, aRowOff, bRow0, cSel, acc);
    }

    int qrow = lane >> 2, qcol = (lane & 3) * 2;
#pragma unroll
    for (int mi = 0; mi < 2; mi++) {
        int r0 = m0 + wm * 32 + mi * 16 + qrow;
#pragma unroll
        for (int ni = 0; ni < 4; ni++) {
            int col = n0 + wn * 32 + ni * 8 + qcol;
            float2 bc = *(const float2*)&bias[col];
            *(float2*)(g_ltmp + (size_t)r0 * HSZ + col) =
                make_float2(fmaxf(acc[mi][ni][0] + bc.x, 0.f),
                            fmaxf(acc[mi][ni][1] + bc.y, 0.f));
            *(float2*)(g_ltmp + (size_t)(r0 + 8) * HSZ + col) =
                make_float2(fmaxf(acc[mi][ni][2] + bc.x, 0.f),
                            fmaxf(acc[mi][ni][3] + bc.y, 0.f));
        }
    }
}

// ---------------------------------------------------------------------------
// Normalize leaf rows -> chart cells (b, t) fp32 + bf16 hi/lo; zero leaf scores.
// ---------------------------------------------------------------------------
__global__ void leaf_norm(float* __restrict__ chart) {
    int r = blockIdx.x;
    int b = r >> 5, t = r & 31;
    int tid = threadIdx.x;            // 128
    const float4* src = (const float4*)(g_ltmp + (size_t)r * HSZ);
    float4 v = src[tid];
    float ss = v.x * v.x + v.y * v.y + v.z * v.z + v.w * v.w;
    __shared__ float red[4];
    __shared__ float s_inv;
    int w = tid >> 5, lane = tid & 31;
#pragma unroll
    for (int o = 16; o > 0; o >>= 1) ss += __shfl_xor_sync(0xffffffffu, ss, o);
    if (lane == 0) red[w] = ss;
    __syncthreads();
    if (tid == 0) {
        float tt = red[0] + red[1] + red[2] + red[3];
        s_inv = 1.f / fmaxf(sqrtf(tt), 1e-12f);
        g_sch[b * NCELL + t] = 0.f;
    }
    __syncthreads();
    float inv = s_inv;
    v.x *= inv; v.y *= inv; v.z *= inv; v.w *= inv;
    size_t base = ((size_t)b * NCELL + t) * HSZ;
    *(float4*)(chart + base + tid * 4) = v;
    float f[4] = {v.x, v.y, v.z, v.w};
    __align__(8) __nv_bfloat16 hi[4], lo[4];
#pragma unroll
    for (int i = 0; i < 4; i++) {
        hi[i] = __float2bfloat16(f[i]);
        lo[i] = __float2bfloat16(f[i] - __bfloat162float(hi[i]));
    }
    *(uint2*)(g_chh + base + tid * 4) = *(const uint2*)hi;
    *(uint2*)(g_chl + base + tid * 4) = *(const uint2*)lo;
}

// ---------------------------------------------------------------------------
// Combine: one block (256 threads) per output cell (b, pos) at `level`.
// Pass 1: fp16 Sh x bf16 h. Pass 2: fp16 A/C, 4 features per thread (128 lanes).
// ---------------------------------------------------------------------------
__global__ __launch_bounds__(256)
void combine_kernel2(float* __restrict__ chart,
                     const float* __restrict__ b_comp,
                     int level) {
    int L = TLEN - level;
    int cidx = blockIdx.x;
    int b = cidx / L, pos = cidx - b * L;
    int cell = b * NCELL + offs(level) + pos;

    __shared__ float sv[32];
    __shared__ float pv[32];
    __shared__ float red[4];
    __shared__ float s_inv;

    int tid = threadIdx.x, w = tid >> 5, lane = tid & 31;

    for (int n = w; n < level; n += 8) {
        int lcell = b * NCELL + offs(n) + pos;
        int rcell = b * NCELL + offs(level - 1 - n) + pos + n + 1;
        const uint2* Sp = (const uint2*)(g_Sh + (size_t)lcell * HSZ);
        const uint2* Hp = (const uint2*)(g_chh + (size_t)rcell * HSZ);
        float d = 0.f;
#pragma unroll
        for (int i = lane; i < 128; i += 32) {
            uint2 sraw = __ldg(Sp + i);
            uint2 hraw = __ldg(Hp + i);
            float2 s0 = __half22float2(*(__half2*)&sraw.x);
            float2 s1 = __half22float2(*(__half2*)&sraw.y);
            float2 h0 = __bfloat1622float2(*(__nv_bfloat162*)&hraw.x);
            float2 h1 = __bfloat1622float2(*(__nv_bfloat162*)&hraw.y);
            d += s0.x * h0.x + s0.y * h0.y + s1.x * h1.x + s1.y * h1.y;
        }
#pragma unroll
        for (int o = 16; o > 0; o >>= 1) d += __shfl_xor_sync(0xffffffffu, d, o);
        if (lane == 0) sv[n] = d + g_sch[lcell] + g_sch[rcell];
    }
    __syncthreads();

    if (w == 0) {
        float s = (lane < level) ? sv[lane] : -1e30f;
        float m = s;
#pragma unroll
        for (int o = 16; o > 0; o >>= 1) m = fmaxf(m, __shfl_xor_sync(0xffffffffu, m, o));
        float e = (lane < level) ? expf(s - m) : 0.f;
        float se = e;
#pragma unroll
        for (int o = 16; o > 0; o >>= 1) se += __shfl_xor_sync(0xffffffffu, se, o);
        float p = e / se;
        pv[lane] = p;
        float sp = (lane < level) ? s * p : 0.f;
#pragma unroll
        for (int o = 16; o > 0; o >>= 1) sp += __shfl_xor_sync(0xffffffffu, sp, o);
        if (lane == 0 && level < TLEN - 1) g_sch[cell] = sp;
    }
    __syncthreads();

    float4 acc = make_float4(0.f, 0.f, 0.f, 0.f);
    int j = (tid & 127) * 4;
    if (tid < 128) {
        const float4 bc = *(const float4*)&b_comp[j];
        int base0 = b * NCELL + pos;
#pragma unroll 4
        for (int n = 0; n < level; n++) {
            int lcell = base0 + offs(n);
            int rcell = base0 + offs(level - 1 - n) + n + 1;
            uint2 Araw = __ldg((const uint2*)(g_ACh + (size_t)lcell * 1024 + j));
            uint2 Craw = __ldg((const uint2*)(g_ACh + (size_t)rcell * 1024 + HSZ + j));
            float2 a0 = __half22float2(*(__half2*)&Araw.x);
            float2 a1 = __half22float2(*(__half2*)&Araw.y);
            float2 c0 = __half22float2(*(__half2*)&Craw.x);
            float2 c1 = __half22float2(*(__half2*)&Craw.y);
            float p = pv[n];
            acc.x += p * fmaxf(a0.x + c0.x + bc.x, 0.f);
            acc.y += p * fmaxf(a0.y + c0.y + bc.y, 0.f);
            acc.z += p * fmaxf(a1.x + c1.x + bc.z, 0.f);
            acc.w += p * fmaxf(a1.y + c1.y + bc.w, 0.f);
        }
        float ss = acc.x * acc.x + acc.y * acc.y + acc.z * acc.z + acc.w * acc.w;
#pragma unroll
        for (int o = 16; o > 0; o >>= 1) ss += __shfl_xor_sync(0xffffffffu, ss, o);
        if (lane == 0) red[w] = ss;
    }
    __syncthreads();
    if (tid == 0) {
        float t = red[0] + red[1] + red[2] + red[3];
        s_inv = 1.f / fmaxf(sqrtf(t), 1e-12f);
    }
    __syncthreads();
    if (tid < 128) {
        float inv = s_inv;
        float4 v = make_float4(acc.x * inv, acc.y * inv, acc.z * inv, acc.w * inv);
        size_t base = (size_t)cell * HSZ;
        *(float4*)(chart + base + j) = v;
        if (level < TLEN - 1) {
            float f[4] = {v.x, v.y, v.z, v.w};
            __align__(8) __nv_bfloat16 hi[4], lo[4];
#pragma unroll
            for (int i = 0; i < 4; i++) {
                hi[i] = __float2bfloat16(f[i]);
                lo[i] = __float2bfloat16(f[i] - __bfloat162float(hi[i]));
            }
            *(uint2*)(g_chh + base + j) = *(const uint2*)hi;
            *(uint2*)(g_chl + base + j) = *(const uint2*)lo;
        }
    }
}

// ---------------------------------------------------------------------------
extern "C" void kernel_launch(void* const* d_in, const int* in_sizes, int n_in,
                              void* d_out, int out_size) {
    const float* x      = (const float*)d_in[0];
    const float* w_leaf = (const float*)d_in[1];
    const float* b_leaf = (const float*)d_in[2];
    const float* w_comp = (const float*)d_in[3];
    const float* b_comp = (const float*)d_in[4];
    const float* s_bil  = (const float*)d_in[5];
    float* chart = (float*)d_out;

    (void)in_sizes; (void)n_in; (void)out_size;

    cudaFuncSetAttribute(proj_mma, cudaFuncAttributeMaxDynamicSharedMemorySize, DSMEM);
    cudaFuncSetAttribute(leaf_mma, cudaFuncAttributeMaxDynamicSharedMemorySize, DSMEM);

    pack_all<<<(WT_ELEMS + X_ELEMS + WL_ELEMS) / 256, 256>>>(
        w_comp, s_bil, x, w_leaf);

    leaf_mma<<<dim3(HSZ / 64, (BATCH * TLEN) / 64), 128, DSMEM>>>(b_leaf);
    leaf_norm<<<BATCH * TLEN, 128>>>(chart);
    proj_mma<<<dim3(NPROJ / 64, (BATCH * TLEN + 63) / 64), 128, DSMEM>>>(
        0, TLEN, BATCH * TLEN);

    for (int level = 1; level < TLEN; level++) {
        int L = TLEN - level;
        combine_kernel2<<<BATCH * L, 256>>>(chart, b_comp, level);
        if (level < TLEN - 1) {
            int M = BATCH * L;
            proj_mma<<<dim3(NPROJ / 64, (M + 63) / 64), 128, DSMEM>>>(
                offs(level), L, M);
        }
    }
}